// round 12
// baseline (speedup 1.0000x reference)
#include <cuda_runtime.h>
#include <cuda_fp16.h>
#include <math.h>
#include <stdint.h>

// Problem dims
#define Bn 16
#define Sn 96
#define Wn 48
#define En 300
#define Hn 256
#define Gn 1024
#define NSq (Bn*Sn)      // 1536
#define NW  (NSq*Wn)     // 73728
#define KPW 320          // padded K for word-level GEMM

// ---------------- static device scratch ----------------
__device__ __align__(16) __half g_wgates[(size_t)NW * 2048];   // fp16 gates (word)
__device__ float g_Ut[4 * Hn * Gn];                  // sl/m2 recurrent weights, k-major fp32
__device__ float g_pooled[(size_t)NSq * 2 * Hn];
__device__ __align__(16) __half g_sgates[(size_t)NSq * 2048];
__device__ float g_hs[(size_t)NSq * 2 * Hn];
__device__ float g_hr[(size_t)NSq * 4 * Hn];
__device__ __align__(16) __half g_mgates[(size_t)NSq * 2048];
__device__ float g_h2[(size_t)NSq * 2 * Hn];
__device__ int   g_cnt1[2 * 16 * 96];
__device__ int   g_cnt2[2 * 16 * 96];
__device__ float g_hbuf[2 * 2 * 16 * 256];
__device__ __align__(16) __half g_ah[(size_t)NW * KPW];
__device__ __align__(16) __half g_bh[2048 * 1024];
__device__ __align__(16) __half g_ubf[2 * 16 * 1024 * 16];  // word U, chunked fp16

__device__ __forceinline__ float sigf(float x) { return 1.0f / (1.0f + expf(-x)); }

__device__ __forceinline__ uint32_t smem_u32(const void* p) {
    uint32_t a;
    asm("{ .reg .u64 t; cvta.to.shared.u64 t, %1; cvt.u32.u64 %0, t; }" : "=r"(a) : "l"(p));
    return a;
}
__device__ __forceinline__ void cpasync16(uint32_t dst, const void* src) {
    asm volatile("cp.async.cg.shared.global [%0], [%1], 16;" :: "r"(dst), "l"(src));
}
__device__ __forceinline__ void ldsm4(uint32_t* r, uint32_t addr) {
    asm volatile("ldmatrix.sync.aligned.m8n8.x4.shared.b16 {%0,%1,%2,%3}, [%4];"
                 : "=r"(r[0]), "=r"(r[1]), "=r"(r[2]), "=r"(r[3]) : "r"(addr));
}
__device__ __forceinline__ void mma_f16(float* c, const uint32_t* a, const uint32_t* b) {
    asm volatile("mma.sync.aligned.m16n8k16.row.col.f32.f16.f16.f32 "
                 "{%0,%1,%2,%3}, {%4,%5,%6,%7}, {%8,%9}, {%0,%1,%2,%3};"
                 : "+f"(c[0]), "+f"(c[1]), "+f"(c[2]), "+f"(c[3])
                 : "r"(a[0]), "r"(a[1]), "r"(a[2]), "r"(a[3]), "r"(b[0]), "r"(b[1]));
}
__device__ __forceinline__ float ex2a(float x) { float y; asm("ex2.approx.f32 %0, %1;" : "=f"(y) : "f"(x)); return y; }
__device__ __forceinline__ float rcpa(float x) { float y; asm("rcp.approx.f32 %0, %1;" : "=f"(y) : "f"(x)); return y; }
__device__ __forceinline__ float fsig(float x) { return rcpa(1.0f + ex2a(-1.4426950408889634f * x)); }
__device__ __forceinline__ float ftanh(float x) { return 1.0f - 2.0f * rcpa(ex2a(2.8853900817779268f * x) + 1.0f); }

// ---------------- fused word-level conversions: x -> ah, Wf|Wb -> bh ----------------
__global__ void conv_all(const float* __restrict__ x,
                         const float* __restrict__ wf, const float* __restrict__ wb,
                         __half* __restrict__ ah, __half* __restrict__ bh)
{
    size_t idx = (size_t)blockIdx.x * 256 + threadIdx.x;
    const size_t nA = (size_t)NW * KPW;
    const size_t nW = (size_t)1024 * KPW;
    if (idx < nA) {
        size_t m = idx / KPW;
        int k = (int)(idx - m * KPW);
        ah[idx] = __float2half((k < En) ? x[m * En + k] : 0.f);
    } else if (idx < nA + nW) {
        size_t i = idx - nA;
        size_t m = i / KPW;
        int k = (int)(i - m * KPW);
        bh[i] = __float2half((k < En) ? wf[m * En + k] : 0.f);
    } else if (idx < nA + 2 * nW) {
        size_t i = idx - nA - nW;
        size_t m = i / KPW;
        int k = (int)(i - m * KPW);
        bh[nW + i] = __float2half((k < En) ? wb[m * En + k] : 0.f);
    }
}

// ---------------- fp32 -> fp16 single with K padding ----------------
__global__ void conv_w(const float* __restrict__ src, __half* __restrict__ dst,
                       int M, int K, int Kp)
{
    size_t idx = (size_t)blockIdx.x * 256 + threadIdx.x;
    if (idx >= (size_t)M * Kp) return;
    size_t m = idx / Kp;
    int k = (int)(idx - m * Kp);
    float v = (k < K) ? src[m * K + k] : 0.f;
    dst[idx] = __float2half(v);
}

// word-level recurrent U -> chunked fp16 layout [dir][chunk16][n1024][k16]
__global__ void conv_u(const float* __restrict__ uf, const float* __restrict__ ub,
                       __half* __restrict__ dst)
{
    int idx = blockIdx.x * 256 + threadIdx.x;
    if (idx >= 2 * 1024 * 256) return;
    int dir = idx >> 18;
    int rem = idx & 262143;
    int n = rem >> 8;
    int kk = rem & 255;
    const float* U = dir ? ub : uf;
    float v = U[n * 256 + kk];
    int c = kk >> 4, k = kk & 15;
    dst[(((size_t)dir * 16 + c) * 1024 + n) * 16 + k] = __float2half(v);
}

// ---------------- transpose U (1024x256 -> 256x1024), 4 matrices (sl/m2, fp32) ----------------
__global__ void transpose_u(const float* __restrict__ u0, const float* __restrict__ u1,
                            const float* __restrict__ u2, const float* __restrict__ u3,
                            float* __restrict__ ut)
{
    __shared__ float tile[32][33];
    int m = blockIdx.z;
    const float* U = (m == 0) ? u0 : (m == 1) ? u1 : (m == 2) ? u2 : u3;
    int g0 = blockIdx.x * 32;
    int k0 = blockIdx.y * 32;
    int tx = threadIdx.x, ty = threadIdx.y;
#pragma unroll
    for (int i = 0; i < 4; i++)
        tile[ty + 8 * i][tx] = U[(size_t)(g0 + ty + 8 * i) * Hn + k0 + tx];
    __syncthreads();
    float* Ut = ut + (size_t)m * Hn * Gn;
#pragma unroll
    for (int i = 0; i < 4; i++)
        Ut[(size_t)(k0 + ty + 8 * i) * Gn + g0 + tx] = tile[tx][ty + 8 * i];
}

// ---------------- fp16 GEMM via mma.sync: C(half) = A @ B^T + bias ----------------
#define STAGE_B   20480
#define OFF_BH    10240

__global__ void __launch_bounds__(256, 2) gemm_mma(
    const __half* __restrict__ Ah, const __half* __restrict__ Bh,
    const float* __restrict__ biasF, const float* __restrict__ biasB,
    __half* __restrict__ C, int Kp)
{
    extern __shared__ char smem[];
    uint32_t sb = smem_u32(smem);
    int tid = threadIdx.x;
    int lane = tid & 31, wid = tid >> 5;
    int m0 = blockIdx.y * 128;
    int n0 = blockIdx.x * 128;
    int wm = (wid & 1) * 64;
    int wn = (wid >> 1) * 32;
    int nk = Kp / 32;

    float acc[4][4][4];
#pragma unroll
    for (int i = 0; i < 4; i++)
#pragma unroll
        for (int j = 0; j < 4; j++)
#pragma unroll
            for (int k = 0; k < 4; k++) acc[i][j][k] = 0.f;

    int ur = tid >> 2;
    int uc = tid & 3;

    auto load_stage = [&](int kc, int buf) {
        uint32_t dbase = sb + buf * STAGE_B;
#pragma unroll
        for (int rep = 0; rep < 2; rep++) {
            int r = ur + rep * 64;
            uint32_t doff = (uint32_t)r * 80 + uc * 16;
            size_t srcA = (size_t)(m0 + r) * Kp + kc * 32 + uc * 8;
            size_t srcB = (size_t)(n0 + r) * Kp + kc * 32 + uc * 8;
            cpasync16(dbase + doff,          Ah + srcA);
            cpasync16(dbase + OFF_BH + doff, Bh + srcB);
        }
    };

    load_stage(0, 0);
    asm volatile("cp.async.commit_group;" ::: "memory");

#pragma unroll 1
    for (int kc = 0; kc < nk; kc++) {
        if (kc + 1 < nk) load_stage(kc + 1, (kc + 1) & 1);
        asm volatile("cp.async.commit_group;" ::: "memory");
        asm volatile("cp.async.wait_group 1;" ::: "memory");
        __syncthreads();

        uint32_t base = sb + (kc & 1) * STAGE_B;
#pragma unroll
        for (int kk = 0; kk < 32; kk += 16) {
            uint32_t ah[4][4];
#pragma unroll
            for (int mt = 0; mt < 4; mt++) {
                int row = wm + mt * 16 + (lane & 15);
                int col = kk + ((lane >> 4) << 3);
                ldsm4(ah[mt], base + (uint32_t)row * 80 + col * 2);
            }
            uint32_t bh[2][4];
#pragma unroll
            for (int bt = 0; bt < 2; bt++) {
                int row = wn + bt * 16 + ((lane >> 4) << 3) + (lane & 7);
                int col = kk + (((lane >> 3) & 1) << 3);
                ldsm4(bh[bt], base + OFF_BH + (uint32_t)row * 80 + col * 2);
            }
#pragma unroll
            for (int mt = 0; mt < 4; mt++) {
#pragma unroll
                for (int nt = 0; nt < 4; nt++) {
                    const uint32_t* fh = &bh[nt >> 1][(nt & 1) * 2];
                    mma_f16(acc[mt][nt], ah[mt], fh);
                }
            }
        }
        __syncthreads();
    }

    const float* bp = (n0 < 1024) ? (biasF + n0) : (biasB + (n0 - 1024));
#pragma unroll
    for (int mt = 0; mt < 4; mt++) {
        int r0 = m0 + wm + mt * 16 + (lane >> 2);
#pragma unroll
        for (int nt = 0; nt < 4; nt++) {
            int col = wn + nt * 8 + 2 * (lane & 3);
            float2 bv = *(const float2*)(bp + col);
            __half2 v0 = __floats2half2_rn(acc[mt][nt][0] + bv.x, acc[mt][nt][1] + bv.y);
            __half2 v1 = __floats2half2_rn(acc[mt][nt][2] + bv.x, acc[mt][nt][3] + bv.y);
            *(__half2*)&C[(size_t)r0 * 2048 + n0 + col] = v0;
            *(__half2*)&C[(size_t)(r0 + 8) * 2048 + n0 + col] = v1;
        }
    }
}

// ---------------- word-level LSTM via mma.sync (fp16), 32 seqs/block, 512 threads ----------------
#define LW_USTG   16896
#define LW_G      16896
#define LW_C      148992
#define LW_LEN    181760
#define LW_SMEM   181888

__global__ void __launch_bounds__(512, 1) lstm_word_mma(
    const __half* __restrict__ gates, const __half* __restrict__ ubf,
    const int* __restrict__ slen, const int* __restrict__ dlen,
    float* __restrict__ pooled)
{
    extern __shared__ char sm[];
    uint32_t sb = smem_u32(sm);
    int tid = threadIdx.x;
    int lane = tid & 31, wid = tid >> 5;   // 16 warps
    int n0 = blockIdx.x * 32;
    int dir = blockIdx.y;
    const char* Usrc = (const char*)(ubf + (size_t)dir * (16 * 1024 * 16));

    for (int i = tid; i < 16896 / 4; i += 512) ((float*)sm)[i] = 0.f;
    for (int i = tid; i < 8192; i += 512) ((float*)(sm + LW_C))[i] = 0.f;
    int* lensh = (int*)(sm + LW_LEN);
    if (tid < 32) lensh[tid] = slen[n0 + tid];
    float hm[16];
#pragma unroll
    for (int i = 0; i < 16; i++) hm[i] = -INFINITY;
    __syncthreads();

    float* Gs = (float*)(sm + LW_G);
    float* Cs = (float*)(sm + LW_C);

    auto load_chunk = [&](int c, int buf) {
        uint32_t dst = sb + LW_USTG + buf * 32768;
        const char* src = Usrc + (size_t)c * 32768;
#pragma unroll
        for (int it = 0; it < 4; it++) {
            int seg = it * 512 + tid;
            cpasync16(dst + seg * 16, src + seg * 16);
        }
    };

    int jj = tid & 255, sh = tid >> 8;

#pragma unroll 1
    for (int step = 0; step < Wn; ++step) {
        int t = dir ? (Wn - 1 - step) : step;

        float acc[2][8][4];
#pragma unroll
        for (int mt = 0; mt < 2; mt++)
#pragma unroll
            for (int nt = 0; nt < 8; nt++)
#pragma unroll
                for (int k = 0; k < 4; k++) acc[mt][nt][k] = 0.f;

        load_chunk(0, 0);
        asm volatile("cp.async.commit_group;" ::: "memory");

#pragma unroll 1
        for (int c = 0; c < 16; c++) {
            if (c + 1 < 16) load_chunk(c + 1, (c + 1) & 1);
            asm volatile("cp.async.commit_group;" ::: "memory");
            asm volatile("cp.async.wait_group 1;" ::: "memory");
            __syncthreads();

            uint32_t ub0 = sb + LW_USTG + (c & 1) * 32768;
            uint32_t ah[2][4];
#pragma unroll
            for (int mt = 0; mt < 2; mt++) {
                int row = mt * 16 + (lane & 15);
                int col = c * 16 + ((lane >> 4) << 3);
                ldsm4(ah[mt], sb + (uint32_t)row * 528 + col * 2);
            }
            uint32_t bh[4][4];
#pragma unroll
            for (int bt = 0; bt < 4; bt++) {
                int row = wid * 64 + bt * 16 + ((lane >> 4) << 3) + (lane & 7);
                int col = (((lane >> 3) & 1) << 3);
                ldsm4(bh[bt], ub0 + (uint32_t)row * 32 + col * 2);
            }
#pragma unroll
            for (int mt = 0; mt < 2; mt++) {
#pragma unroll
                for (int nt = 0; nt < 8; nt++) {
                    const uint32_t* fh = &bh[nt >> 1][(nt & 1) * 2];
                    mma_f16(acc[mt][nt], ah[mt], fh);
                }
            }
            __syncthreads();
        }

        // write G
#pragma unroll
        for (int mt = 0; mt < 2; mt++) {
            int row0 = mt * 16 + (lane >> 2);
#pragma unroll
            for (int nt = 0; nt < 8; nt++) {
                int colb = wid * 64 + nt * 8 + (lane & 3) * 2;
                Gs[row0 * 1032 + colb]     = acc[mt][nt][0];
                Gs[row0 * 1032 + colb + 1] = acc[mt][nt][1];
                Gs[(row0 + 8) * 1032 + colb]     = acc[mt][nt][2];
                Gs[(row0 + 8) * 1032 + colb + 1] = acc[mt][nt][3];
            }
        }
        __syncthreads();

        // activations: 16 (s,j) pairs per thread
#pragma unroll 4
        for (int i = 0; i < 16; i++) {
            int s = sh * 16 + i;
            const __half* gp = gates + (((size_t)(n0 + s)) * Wn + t) * 2048 + (size_t)dir * 1024;
            float ai = __half2float(gp[jj])       + Gs[s * 1032 + jj];
            float af = __half2float(gp[256 + jj]) + Gs[s * 1032 + 256 + jj];
            float ag = __half2float(gp[512 + jj]) + Gs[s * 1032 + 512 + jj];
            float ao = __half2float(gp[768 + jj]) + Gs[s * 1032 + 768 + jj];
            float cc = Cs[s * 256 + jj];
            cc = fsig(af) * cc + fsig(ai) * ftanh(ag);
            Cs[s * 256 + jj] = cc;
            float h = fsig(ao) * ftanh(cc);
            if (t < lensh[s]) hm[i] = fmaxf(hm[i], h);
            *(__half*)(sm + (size_t)s * 528 + jj * 2) = __float2half(h);
        }
        __syncthreads();
    }

#pragma unroll
    for (int i = 0; i < 16; i++) {
        int s = sh * 16 + i;
        int n = n0 + s;
        int bb = n / Sn, sr = n % Sn;
        float v = (sr < dlen[bb]) ? hm[i] : 0.f;
        pooled[(size_t)n * 512 + (size_t)dir * 256 + jj] = v;
    }
}

// ---------------- sequence-level LSTM: 4-way N-split, global spin barrier per step ----------------
__global__ void __launch_bounds__(256) lstm_seq4(const __half* __restrict__ gates,
                                                 const float* __restrict__ ut, int ubase,
                                                 const int* __restrict__ dlen,
                                                 float* __restrict__ out, int mask,
                                                 int* __restrict__ cnt, float* __restrict__ hbuf)
{
    int ns = blockIdx.x;     // 0..3
    int b = blockIdx.y;
    int dir = blockIdx.z;
    int tid = threadIdx.x;
    int u0 = ns * 64;
    int gate = tid >> 6, ul = tid & 63;
    int g = gate * 256 + u0 + ul;
    const float* U = ut + (size_t)(ubase + dir) * Hn * Gn;
    __shared__ float hsh[256];
    __shared__ float gsh[256];
    float c = 0.f;
    int dl = dlen[b];
    float* hb0 = hbuf + ((size_t)(0 * 2 + dir) * 16 + b) * 256;
    float* hb1 = hbuf + ((size_t)(1 * 2 + dir) * 16 + b) * 256;
    int* mycnt = cnt + (dir * 16 + b) * 96;
    hsh[tid] = 0.f;
    __syncthreads();

#pragma unroll 1
    for (int step = 0; step < Sn; ++step) {
        int t = dir ? (Sn - 1 - step) : step;
        float acc = __half2float(gates[((size_t)b * Sn + t) * 2048 + (size_t)dir * 1024 + g]);
#pragma unroll 8
        for (int k = 0; k < Hn; k++)
            acc = fmaf(U[(size_t)k * Gn + g], hsh[k], acc);
        gsh[tid] = acc;
        __syncthreads();
        float* hw = (step & 1) ? hb1 : hb0;
        if (tid < 64) {
            float fi = sigf(gsh[tid]), ff = sigf(gsh[64 + tid]);
            float fg = tanhf(gsh[128 + tid]), fo = sigf(gsh[192 + tid]);
            c = ff * c + fi * fg;
            float h = fo * tanhf(c);
            hw[u0 + tid] = h;
            float o = (!mask || t < dl) ? h : 0.f;
            out[((size_t)b * Sn + t) * 512 + (size_t)dir * 256 + u0 + tid] = o;
        }
        __syncthreads();
        if (tid == 0) {
            __threadfence();
            atomicAdd(&mycnt[step], 1);
            while (atomicAdd(&mycnt[step], 0) < 4) { }
            __threadfence();
        }
        __syncthreads();
        hsh[tid] = hw[tid];
        __syncthreads();
    }
}

// ---------------- block reduction helper ----------------
__device__ __forceinline__ float blockReduce256(float v, volatile float* red)
{
#pragma unroll
    for (int o = 16; o > 0; o >>= 1) v += __shfl_down_sync(0xffffffffu, v, o);
    if ((threadIdx.x & 31) == 0) red[threadIdx.x >> 5] = v;
    __syncthreads();
    float r = red[0] + red[1] + red[2] + red[3] + red[4] + red[5] + red[6] + red[7];
    __syncthreads();
    return r;
}

// ---------------- restricted window attention ----------------
__global__ void __launch_bounds__(256) attn_kernel(const float* __restrict__ hs,
                                                   const float* __restrict__ attn_w,
                                                   const float* __restrict__ attn_b,
                                                   const int* __restrict__ dlen,
                                                   float* __restrict__ hr)
{
    __shared__ float red[8];
    __shared__ float sc[7];
    __shared__ float awt[7];
    int bs = blockIdx.x;
    int b = bs / Sn, s = bs % Sn;
    int tid = threadIdx.x;
    int dl = dlen[b];
    const float* X = hs + (size_t)bs * 512;

    float pxx = 0.f, pxw = 0.f;
    for (int d = tid; d < 512; d += 256) {
        float v = X[d];
        pxx += v * v;
        pxw += v * attn_w[512 + d];
    }
    float nx2 = blockReduce256(pxx, red);
    float xw2 = blockReduce256(pxw, red);
    float nxc = fmaxf(sqrtf(nx2), 1e-12f);

    for (int k = 0; k < 7; k++) {
        int idx = s - 3 + k;
        int idc = min(max(idx, 0), Sn - 1);
        const float* Xw = hs + ((size_t)b * Sn + idc) * 512;
        float pa = 0.f, pb = 0.f, pc = 0.f;
        for (int d = tid; d < 512; d += 256) {
            float w = Xw[d];
            pa += w * X[d];
            pb += w * w;
            pc += w * attn_w[d];
        }
        float dwx = blockReduce256(pa, red);
        float nw2 = blockReduce256(pb, red);
        float dw0 = blockReduce256(pc, red);
        if (tid == 0) {
            float sim = sigf(dwx / (fmaxf(sqrtf(nw2), 1e-12f) * nxc));
            float sco = dw0 + xw2 + sim * attn_w[1024] + attn_b[0];
            bool valid = (idx >= 0) && (idx < dl) && (s < dl);
            sc[k] = valid ? sco : -1e30f;
        }
    }
    __syncthreads();
    if (tid == 0) {
        float m = sc[0];
#pragma unroll
        for (int k = 1; k < 7; k++) m = fmaxf(m, sc[k]);
        float sum = 0.f;
#pragma unroll
        for (int k = 0; k < 7; k++) { float e = expf(sc[k] - m); awt[k] = e; sum += e; }
        float inv = 1.f / sum;
#pragma unroll
        for (int k = 0; k < 7; k++) awt[k] *= inv;
    }
    __syncthreads();
    for (int d = tid; d < 512; d += 256) {
        float acc = 0.f;
#pragma unroll
        for (int k = 0; k < 7; k++) {
            int idc = min(max(s - 3 + k, 0), Sn - 1);
            acc += awt[k] * hs[((size_t)b * Sn + idc) * 512 + d];
        }
        hr[(size_t)bs * 1024 + d] = X[d];
        hr[(size_t)bs * 1024 + 512 + d] = (s < dl) ? acc : 0.f;
    }
}

// ---------------- classifier + softmax(2) ----------------
__global__ void __launch_bounds__(128) cls_kernel(const float* __restrict__ h2,
                                                  const float* __restrict__ clsW,
                                                  const float* __restrict__ clsb,
                                                  float* __restrict__ out)
{
    __shared__ float r0s[4], r1s[4];
    int bs = blockIdx.x;
    int tid = threadIdx.x;
    const float* h = h2 + (size_t)bs * 512;
    float p0 = 0.f, p1 = 0.f;
    for (int d = tid; d < 512; d += 128) {
        float v = h[d];
        p0 += v * clsW[d];
        p1 += v * clsW[512 + d];
    }
#pragma unroll
    for (int o = 16; o > 0; o >>= 1) {
        p0 += __shfl_down_sync(0xffffffffu, p0, o);
        p1 += __shfl_down_sync(0xffffffffu, p1, o);
    }
    if ((tid & 31) == 0) { r0s[tid >> 5] = p0; r1s[tid >> 5] = p1; }
    __syncthreads();
    if (tid == 0) {
        float l0 = r0s[0] + r0s[1] + r0s[2] + r0s[3] + clsb[0];
        float l1 = r1s[0] + r1s[1] + r1s[2] + r1s[3] + clsb[1];
        float m = fmaxf(l0, l1);
        float e0 = expf(l0 - m), e1 = expf(l1 - m);
        float inv = 1.f / (e0 + e1);
        out[(size_t)bs * 2 + 0] = e0 * inv;
        out[(size_t)bs * 2 + 1] = e1 * inv;
    }
}

// ---------------- launch ----------------
extern "C" void kernel_launch(void* const* d_in, const int* in_sizes, int n_in,
                              void* d_out, int out_size)
{
    const float* x     = (const float*)d_in[0];
    const int*   slen  = (const int*)d_in[1];
    const int*   dlen  = (const int*)d_in[2];
    const float* wl_Wf = (const float*)d_in[3];
    const float* wl_Uf = (const float*)d_in[4];
    const float* wl_bf = (const float*)d_in[5];
    const float* wl_Wb = (const float*)d_in[6];
    const float* wl_Ub = (const float*)d_in[7];
    const float* wl_bb = (const float*)d_in[8];
    const float* sl_Wf = (const float*)d_in[9];
    const float* sl_Uf = (const float*)d_in[10];
    const float* sl_bf = (const float*)d_in[11];
    const float* sl_Wb = (const float*)d_in[12];
    const float* sl_Ub = (const float*)d_in[13];
    const float* sl_bb = (const float*)d_in[14];
    const float* attn_w = (const float*)d_in[15];
    const float* attn_b = (const float*)d_in[16];
    const float* m2_Wf = (const float*)d_in[17];
    const float* m2_Uf = (const float*)d_in[18];
    const float* m2_bf = (const float*)d_in[19];
    const float* m2_Wb = (const float*)d_in[20];
    const float* m2_Ub = (const float*)d_in[21];
    const float* m2_bb = (const float*)d_in[22];
    const float* cls_W = (const float*)d_in[23];
    const float* cls_b = (const float*)d_in[24];
    float* out = (float*)d_out;

    float *ut, *pl, *hs, *hr, *h2, *hbuf;
    int *cnt1, *cnt2;
    __half *wg, *sg, *mg, *ah, *bh, *ubf;
    cudaGetSymbolAddress((void**)&wg, g_wgates);
    cudaGetSymbolAddress((void**)&ut, g_Ut);
    cudaGetSymbolAddress((void**)&pl, g_pooled);
    cudaGetSymbolAddress((void**)&sg, g_sgates);
    cudaGetSymbolAddress((void**)&hs, g_hs);
    cudaGetSymbolAddress((void**)&hr, g_hr);
    cudaGetSymbolAddress((void**)&mg, g_mgates);
    cudaGetSymbolAddress((void**)&h2, g_h2);
    cudaGetSymbolAddress((void**)&hbuf, g_hbuf);
    cudaGetSymbolAddress((void**)&cnt1, g_cnt1);
    cudaGetSymbolAddress((void**)&cnt2, g_cnt2);
    cudaGetSymbolAddress((void**)&ah, g_ah);
    cudaGetSymbolAddress((void**)&bh, g_bh);
    cudaGetSymbolAddress((void**)&ubf, g_ubf);

    cudaFuncSetAttribute(gemm_mma, cudaFuncAttributeMaxDynamicSharedMemorySize, 2 * STAGE_B);
    cudaFuncSetAttribute(lstm_word_mma, cudaFuncAttributeMaxDynamicSharedMemorySize, LW_SMEM);

    // --- order: [0] conv_all [1] conv_u [2] gemm(word) [3] lstm_word  (ncu captures +2 offset = lstm_word) ---
    {
        size_t total = (size_t)NW * KPW + 2 * (size_t)1024 * KPW;
        conv_all<<<(int)((total + 255) / 256), 256>>>(x, wl_Wf, wl_Wb, ah, bh);
    }
    conv_u<<<(2 * 1024 * 256 + 255) / 256, 256>>>(wl_Uf, wl_Ub, ubf);
    gemm_mma<<<dim3(16, NW / 128), 256, 2 * STAGE_B>>>(ah, bh, wl_bf, wl_bb, wg, KPW);
    lstm_word_mma<<<dim3(48, 2), 512, LW_SMEM>>>(wg, ubf, slen, dlen, pl);

    // prep for sequence-level LSTMs
    transpose_u<<<dim3(32, 8, 4), dim3(32, 8)>>>(sl_Uf, sl_Ub, m2_Uf, m2_Ub, ut);
    cudaMemsetAsync(cnt1, 0, 2 * 16 * 96 * sizeof(int));
    cudaMemsetAsync(cnt2, 0, 2 * 16 * 96 * sizeof(int));

    // sentence-level: convert + GEMM + recurrence
    conv_w<<<(NSq * 512 + 255) / 256, 256>>>(pl, ah, NSq, 512, 512);
    conv_w<<<(1024 * 512 + 255) / 256, 256>>>(sl_Wf, bh, 1024, 512, 512);
    conv_w<<<(1024 * 512 + 255) / 256, 256>>>(sl_Wb, bh + 1024 * 512, 1024, 512, 512);
    gemm_mma<<<dim3(16, NSq / 128), 256, 2 * STAGE_B>>>(ah, bh, sl_bf, sl_bb, sg, 512);
    lstm_seq4<<<dim3(4, Bn, 2), 256>>>(sg, ut, 0, dlen, hs, 1, cnt1, hbuf);

    // restricted attention
    attn_kernel<<<NSq, 256>>>(hs, attn_w, attn_b, dlen, hr);

    // m2 level: convert + GEMM + recurrence
    conv_w<<<(NSq * 1024 + 255) / 256, 256>>>(hr, ah, NSq, 1024, 1024);
    conv_w<<<(1024 * 1024 + 255) / 256, 256>>>(m2_Wf, bh, 1024, 1024, 1024);
    conv_w<<<(1024 * 1024 + 255) / 256, 256>>>(m2_Wb, bh + 1024 * 1024, 1024, 1024, 1024);
    gemm_mma<<<dim3(16, NSq / 128), 256, 2 * STAGE_B>>>(ah, bh, m2_bf, m2_bb, mg, 1024);
    lstm_seq4<<<dim3(4, Bn, 2), 256>>>(mg, ut, 2, dlen, h2, 0, cnt2, hbuf);

    // classifier + softmax
    cls_kernel<<<NSq, 128>>>(h2, cls_W, cls_b, out);
}

// round 15
// speedup vs baseline: 1.0682x; 1.0682x over previous
#include <cuda_runtime.h>
#include <cuda_fp16.h>
#include <math.h>
#include <stdint.h>

// Problem dims
#define Bn 16
#define Sn 96
#define Wn 48
#define En 300
#define Hn 256
#define Gn 1024
#define NSq (Bn*Sn)      // 1536
#define NW  (NSq*Wn)     // 73728
#define KPW 320          // padded K for word-level GEMM

// ---------------- static device scratch ----------------
__device__ __align__(16) __half g_wgates[(size_t)NW * 2048];   // fp16 gates (word)
__device__ float g_Ut[4 * Hn * Gn];                  // sl/m2 recurrent weights, k-major fp32
__device__ float g_pooled[(size_t)NSq * 2 * Hn];
__device__ __align__(16) __half g_sgates[(size_t)NSq * 2048];
__device__ float g_hs[(size_t)NSq * 2 * Hn];
__device__ float g_hr[(size_t)NSq * 4 * Hn];
__device__ __align__(16) __half g_mgates[(size_t)NSq * 2048];
__device__ float g_h2[(size_t)NSq * 2 * Hn];
__device__ int   g_cnt0[2 * 16 * 144];
__device__ int   g_cnt1[2 * 16 * 96];
__device__ int   g_cnt2[2 * 16 * 96];
__device__ float g_hbuf[2 * 2 * 16 * 256];
__device__ float g_hwb[2 * 16 * 2 * 32 * 256];       // word-level h exchange [dir][slot][buf][s][256]
__device__ __align__(16) __half g_ah[(size_t)NW * KPW];
__device__ __align__(16) __half g_bh[2048 * 1024];
__device__ __align__(16) __half g_ubq[2 * 4 * 256 * 256];  // word U [dir][quarter][localcol][k] fp16

__device__ __forceinline__ float sigf(float x) { return 1.0f / (1.0f + expf(-x)); }

__device__ __forceinline__ uint32_t smem_u32(const void* p) {
    uint32_t a;
    asm("{ .reg .u64 t; cvta.to.shared.u64 t, %1; cvt.u32.u64 %0, t; }" : "=r"(a) : "l"(p));
    return a;
}
__device__ __forceinline__ void cpasync16(uint32_t dst, const void* src) {
    asm volatile("cp.async.cg.shared.global [%0], [%1], 16;" :: "r"(dst), "l"(src));
}
__device__ __forceinline__ void ldsm4(uint32_t* r, uint32_t addr) {
    asm volatile("ldmatrix.sync.aligned.m8n8.x4.shared.b16 {%0,%1,%2,%3}, [%4];"
                 : "=r"(r[0]), "=r"(r[1]), "=r"(r[2]), "=r"(r[3]) : "r"(addr));
}
__device__ __forceinline__ void mma_f16(float* c, const uint32_t* a, const uint32_t* b) {
    asm volatile("mma.sync.aligned.m16n8k16.row.col.f32.f16.f16.f32 "
                 "{%0,%1,%2,%3}, {%4,%5,%6,%7}, {%8,%9}, {%0,%1,%2,%3};"
                 : "+f"(c[0]), "+f"(c[1]), "+f"(c[2]), "+f"(c[3])
                 : "r"(a[0]), "r"(a[1]), "r"(a[2]), "r"(a[3]), "r"(b[0]), "r"(b[1]));
}
__device__ __forceinline__ float ex2a(float x) { float y; asm("ex2.approx.f32 %0, %1;" : "=f"(y) : "f"(x)); return y; }
__device__ __forceinline__ float rcpa(float x) { float y; asm("rcp.approx.f32 %0, %1;" : "=f"(y) : "f"(x)); return y; }
__device__ __forceinline__ float fsig(float x) { return rcpa(1.0f + ex2a(-1.4426950408889634f * x)); }
__device__ __forceinline__ float ftanh(float x) { return 1.0f - 2.0f * rcpa(ex2a(2.8853900817779268f * x) + 1.0f); }

// ---------------- fused word-level conversions: x -> ah, Wf|Wb -> bh ----------------
__global__ void conv_all(const float* __restrict__ x,
                         const float* __restrict__ wf, const float* __restrict__ wb,
                         __half* __restrict__ ah, __half* __restrict__ bh)
{
    size_t idx = (size_t)blockIdx.x * 256 + threadIdx.x;
    const size_t nA = (size_t)NW * KPW;
    const size_t nW = (size_t)1024 * KPW;
    if (idx < nA) {
        size_t m = idx / KPW;
        int k = (int)(idx - m * KPW);
        ah[idx] = __float2half((k < En) ? x[m * En + k] : 0.f);
    } else if (idx < nA + nW) {
        size_t i = idx - nA;
        size_t m = i / KPW;
        int k = (int)(i - m * KPW);
        bh[i] = __float2half((k < En) ? wf[m * En + k] : 0.f);
    } else if (idx < nA + 2 * nW) {
        size_t i = idx - nA - nW;
        size_t m = i / KPW;
        int k = (int)(i - m * KPW);
        bh[nW + i] = __float2half((k < En) ? wb[m * En + k] : 0.f);
    }
}

// ---------------- fp32 -> fp16 single with K padding ----------------
__global__ void conv_w(const float* __restrict__ src, __half* __restrict__ dst,
                       int M, int K, int Kp)
{
    size_t idx = (size_t)blockIdx.x * 256 + threadIdx.x;
    if (idx >= (size_t)M * Kp) return;
    size_t m = idx / Kp;
    int k = (int)(idx - m * Kp);
    float v = (k < K) ? src[m * K + k] : 0.f;
    dst[idx] = __float2half(v);
}

// word-level recurrent U -> per-quarter layout [dir][q][localcol(gate*64+ul)][k]
__global__ void conv_uq(const float* __restrict__ uf, const float* __restrict__ ub,
                        __half* __restrict__ dst)
{
    int idx = blockIdx.x * 256 + threadIdx.x;
    if (idx >= 2 * 4 * 256 * 256) return;
    int dir = idx >> 18;
    int rem = idx & 262143;
    int q = rem >> 16;
    int rem2 = rem & 65535;
    int lc = rem2 >> 8;          // local column (fixed: was k)
    int k  = rem2 & 255;         // k dim       (fixed: was lc)
    int gate = lc >> 6, ul = lc & 63;
    int gcol = gate * 256 + q * 64 + ul;
    const float* U = dir ? ub : uf;
    dst[idx] = __float2half(U[gcol * 256 + k]);
}

// ---------------- transpose U (1024x256 -> 256x1024), 4 matrices (sl/m2, fp32) ----------------
__global__ void transpose_u(const float* __restrict__ u0, const float* __restrict__ u1,
                            const float* __restrict__ u2, const float* __restrict__ u3,
                            float* __restrict__ ut)
{
    __shared__ float tile[32][33];
    int m = blockIdx.z;
    const float* U = (m == 0) ? u0 : (m == 1) ? u1 : (m == 2) ? u2 : u3;
    int g0 = blockIdx.x * 32;
    int k0 = blockIdx.y * 32;
    int tx = threadIdx.x, ty = threadIdx.y;
#pragma unroll
    for (int i = 0; i < 4; i++)
        tile[ty + 8 * i][tx] = U[(size_t)(g0 + ty + 8 * i) * Hn + k0 + tx];
    __syncthreads();
    float* Ut = ut + (size_t)m * Hn * Gn;
#pragma unroll
    for (int i = 0; i < 4; i++)
        Ut[(size_t)(k0 + ty + 8 * i) * Gn + g0 + tx] = tile[tx][ty + 8 * i];
}

// ---------------- fp16 GEMM via mma.sync: C(half) = A @ B^T + bias ----------------
#define STAGE_B   20480
#define OFF_BH    10240

__global__ void __launch_bounds__(256, 2) gemm_mma(
    const __half* __restrict__ Ah, const __half* __restrict__ Bh,
    const float* __restrict__ biasF, const float* __restrict__ biasB,
    __half* __restrict__ C, int Kp)
{
    extern __shared__ char smem[];
    uint32_t sb = smem_u32(smem);
    int tid = threadIdx.x;
    int lane = tid & 31, wid = tid >> 5;
    int m0 = blockIdx.y * 128;
    int n0 = blockIdx.x * 128;
    int wm = (wid & 1) * 64;
    int wn = (wid >> 1) * 32;
    int nk = Kp / 32;

    float acc[4][4][4];
#pragma unroll
    for (int i = 0; i < 4; i++)
#pragma unroll
        for (int j = 0; j < 4; j++)
#pragma unroll
            for (int k = 0; k < 4; k++) acc[i][j][k] = 0.f;

    int ur = tid >> 2;
    int uc = tid & 3;

    auto load_stage = [&](int kc, int buf) {
        uint32_t dbase = sb + buf * STAGE_B;
#pragma unroll
        for (int rep = 0; rep < 2; rep++) {
            int r = ur + rep * 64;
            uint32_t doff = (uint32_t)r * 80 + uc * 16;
            size_t srcA = (size_t)(m0 + r) * Kp + kc * 32 + uc * 8;
            size_t srcB = (size_t)(n0 + r) * Kp + kc * 32 + uc * 8;
            cpasync16(dbase + doff,          Ah + srcA);
            cpasync16(dbase + OFF_BH + doff, Bh + srcB);
        }
    };

    load_stage(0, 0);
    asm volatile("cp.async.commit_group;" ::: "memory");

#pragma unroll 1
    for (int kc = 0; kc < nk; kc++) {
        if (kc + 1 < nk) load_stage(kc + 1, (kc + 1) & 1);
        asm volatile("cp.async.commit_group;" ::: "memory");
        asm volatile("cp.async.wait_group 1;" ::: "memory");
        __syncthreads();

        uint32_t base = sb + (kc & 1) * STAGE_B;
#pragma unroll
        for (int kk = 0; kk < 32; kk += 16) {
            uint32_t ah[4][4];
#pragma unroll
            for (int mt = 0; mt < 4; mt++) {
                int row = wm + mt * 16 + (lane & 15);
                int col = kk + ((lane >> 4) << 3);
                ldsm4(ah[mt], base + (uint32_t)row * 80 + col * 2);
            }
            uint32_t bh[2][4];
#pragma unroll
            for (int bt = 0; bt < 2; bt++) {
                int row = wn + bt * 16 + ((lane >> 4) << 3) + (lane & 7);
                int col = kk + (((lane >> 3) & 1) << 3);
                ldsm4(bh[bt], base + OFF_BH + (uint32_t)row * 80 + col * 2);
            }
#pragma unroll
            for (int mt = 0; mt < 4; mt++) {
#pragma unroll
                for (int nt = 0; nt < 4; nt++) {
                    const uint32_t* fh = &bh[nt >> 1][(nt & 1) * 2];
                    mma_f16(acc[mt][nt], ah[mt], fh);
                }
            }
        }
        __syncthreads();
    }

    const float* bp = (n0 < 1024) ? (biasF + n0) : (biasB + (n0 - 1024));
#pragma unroll
    for (int mt = 0; mt < 4; mt++) {
        int r0 = m0 + wm + mt * 16 + (lane >> 2);
#pragma unroll
        for (int nt = 0; nt < 4; nt++) {
            int col = wn + nt * 8 + 2 * (lane & 3);
            float2 bv = *(const float2*)(bp + col);
            __half2 v0 = __floats2half2_rn(acc[mt][nt][0] + bv.x, acc[mt][nt][1] + bv.y);
            __half2 v1 = __floats2half2_rn(acc[mt][nt][2] + bv.x, acc[mt][nt][3] + bv.y);
            *(__half2*)&C[(size_t)r0 * 2048 + n0 + col] = v0;
            *(__half2*)&C[(size_t)(r0 + 8) * 2048 + n0 + col] = v1;
        }
    }
}

// ---------------- word-level LSTM, persistent-U: 128 blocks (4 quarters x 16 slots x 2 dirs) ----------------
// SMEM: US 256x528 @0 (persistent U slice); HA 32x528 @135168; G 32x264 fp32 @152064; lens @185856.
#define LWP_HA    135168
#define LWP_G     152064
#define LWP_LEN   185856
#define LWP_SMEM  185984

__global__ void __launch_bounds__(512, 1) lstm_word_p(
    const __half* __restrict__ gates, const __half* __restrict__ ubq,
    const int* __restrict__ slen, const int* __restrict__ dlen,
    float* __restrict__ pooled, int* __restrict__ cnt, float* __restrict__ hwb)
{
    extern __shared__ char sm[];
    uint32_t sb = smem_u32(sm);
    int tid = threadIdx.x;
    int lane = tid & 31, wid = tid >> 5;   // 16 warps
    int q = blockIdx.x;       // unit quarter 0..3
    int slot = blockIdx.y;    // 0..15
    int dir = blockIdx.z;

    // one-time load of this block's U slice (256 rows x 512B) into padded smem
    {
        const __half* src = ubq + ((size_t)(dir * 4 + q) * 256) * 256;
#pragma unroll
        for (int i = 0; i < 16; i++) {
            int idx = i * 512 + tid;          // 0..8191
            int row = idx >> 5, seg = idx & 31;
            cpasync16(sb + (uint32_t)row * 528 + seg * 16, src + (size_t)row * 256 + seg * 8);
        }
        asm volatile("cp.async.commit_group;" ::: "memory");
        asm volatile("cp.async.wait_group 0;" ::: "memory");
    }
    __syncthreads();

    float* Gs = (float*)(sm + LWP_G);
    int* lensh = (int*)(sm + LWP_LEN);
    int* mycnt = cnt + (dir * 16 + slot) * 144;
    float* hb0 = hwb + ((size_t)(dir * 16 + slot) * 2 + 0) * 8192;
    float* hb1 = hwb + ((size_t)(dir * 16 + slot) * 2 + 1) * 8192;

    int u = tid & 63, sgrp = tid >> 6;   // thread owns unit u for seqs sgrp*4..sgrp*4+3
    int wn = wid * 16;                   // warp's 16 local gate-cols

#pragma unroll 1
    for (int g = 0; g < 3; g++) {
        int ng = g * 16 + slot;
        int n0 = ng * 32;

        // reset per-group state
        for (int i = tid; i < 16896 / 4; i += 512) ((float*)(sm + LWP_HA))[i] = 0.f;
        if (tid < 32) lensh[tid] = slen[n0 + tid];
        float c[4], hm[4];
#pragma unroll
        for (int i = 0; i < 4; i++) { c[i] = 0.f; hm[i] = -INFINITY; }
        __syncthreads();

#pragma unroll 1
        for (int step = 0; step < Wn; ++step) {
            int t = dir ? (Wn - 1 - step) : step;

            // recurrent mma: G[32 x 256cols] = HA(h prev, fp16) @ US^T
            float acc[2][2][4];
#pragma unroll
            for (int mt = 0; mt < 2; mt++)
#pragma unroll
                for (int nt = 0; nt < 2; nt++)
#pragma unroll
                    for (int k = 0; k < 4; k++) acc[mt][nt][k] = 0.f;

#pragma unroll
            for (int kc = 0; kc < 16; kc++) {
                uint32_t ah[2][4];
#pragma unroll
                for (int mt = 0; mt < 2; mt++) {
                    int row = mt * 16 + (lane & 15);
                    int col = kc * 16 + ((lane >> 4) << 3);
                    ldsm4(ah[mt], sb + LWP_HA + (uint32_t)row * 528 + col * 2);
                }
                uint32_t bf[4];
                {
                    int row = wn + ((lane >> 4) << 3) + (lane & 7);
                    int col = kc * 16 + (((lane >> 3) & 1) << 3);
                    ldsm4(bf, sb + (uint32_t)row * 528 + col * 2);
                }
#pragma unroll
                for (int mt = 0; mt < 2; mt++)
#pragma unroll
                    for (int nt = 0; nt < 2; nt++)
                        mma_f16(acc[mt][nt], ah[mt], &bf[nt * 2]);
            }

            // stage G
#pragma unroll
            for (int mt = 0; mt < 2; mt++) {
                int row0 = mt * 16 + (lane >> 2);
#pragma unroll
                for (int nt = 0; nt < 2; nt++) {
                    int colb = wn + nt * 8 + (lane & 3) * 2;
                    Gs[row0 * 264 + colb]     = acc[mt][nt][0];
                    Gs[row0 * 264 + colb + 1] = acc[mt][nt][1];
                    Gs[(row0 + 8) * 264 + colb]     = acc[mt][nt][2];
                    Gs[(row0 + 8) * 264 + colb + 1] = acc[mt][nt][3];
                }
            }
            __syncthreads();

            // activations: thread (u, sgrp) handles 4 seqs
            float* hw = (step & 1) ? hb1 : hb0;
#pragma unroll
            for (int i = 0; i < 4; i++) {
                int s = sgrp * 4 + i;
                const __half* gp = gates + (((size_t)(n0 + s)) * Wn + t) * 2048 + (size_t)dir * 1024;
                float ai = __half2float(gp[0 * 256 + q * 64 + u]) + Gs[s * 264 + 0 * 64 + u];
                float af = __half2float(gp[1 * 256 + q * 64 + u]) + Gs[s * 264 + 1 * 64 + u];
                float ag = __half2float(gp[2 * 256 + q * 64 + u]) + Gs[s * 264 + 2 * 64 + u];
                float ao = __half2float(gp[3 * 256 + q * 64 + u]) + Gs[s * 264 + 3 * 64 + u];
                c[i] = fsig(af) * c[i] + fsig(ai) * ftanh(ag);
                float h = fsig(ao) * ftanh(c[i]);
                if (t < lensh[s]) hm[i] = fmaxf(hm[i], h);
                hw[s * 256 + q * 64 + u] = h;
            }
            __syncthreads();

            // cross-block barrier among the 4 quarter blocks
            if (tid == 0) {
                __threadfence();
                atomicAdd(&mycnt[g * 48 + step], 1);
                while (atomicAdd(&mycnt[g * 48 + step], 0) < 4) { }
                __threadfence();
            }
            __syncthreads();

            // gather full h into HA (fp16)
#pragma unroll
            for (int i = 0; i < 16; i++) {
                int ii = i * 512 + tid;     // 0..8191
                int s = ii >> 8, col = ii & 255;
                *(__half*)(sm + LWP_HA + (size_t)s * 528 + col * 2) = __float2half(hw[s * 256 + col]);
            }
            __syncthreads();
        }

        // pooled max for this block's units
#pragma unroll
        for (int i = 0; i < 4; i++) {
            int s = sgrp * 4 + i;
            int n = n0 + s;
            int bb = n / Sn, sr = n % Sn;
            float v = (sr < dlen[bb]) ? hm[i] : 0.f;
            pooled[(size_t)n * 512 + (size_t)dir * 256 + q * 64 + u] = v;
        }
        __syncthreads();
    }
}

// ---------------- sequence-level LSTM: 4-way N-split, global spin barrier per step ----------------
__global__ void __launch_bounds__(256) lstm_seq4(const __half* __restrict__ gates,
                                                 const float* __restrict__ ut, int ubase,
                                                 const int* __restrict__ dlen,
                                                 float* __restrict__ out, int mask,
                                                 int* __restrict__ cnt, float* __restrict__ hbuf)
{
    int ns = blockIdx.x;     // 0..3
    int b = blockIdx.y;
    int dir = blockIdx.z;
    int tid = threadIdx.x;
    int u0 = ns * 64;
    int gate = tid >> 6, ul = tid & 63;
    int g = gate * 256 + u0 + ul;
    const float* U = ut + (size_t)(ubase + dir) * Hn * Gn;
    __shared__ float hsh[256];
    __shared__ float gsh[256];
    float c = 0.f;
    int dl = dlen[b];
    float* hb0 = hbuf + ((size_t)(0 * 2 + dir) * 16 + b) * 256;
    float* hb1 = hbuf + ((size_t)(1 * 2 + dir) * 16 + b) * 256;
    int* mycnt = cnt + (dir * 16 + b) * 96;
    hsh[tid] = 0.f;
    __syncthreads();

#pragma unroll 1
    for (int step = 0; step < Sn; ++step) {
        int t = dir ? (Sn - 1 - step) : step;
        float acc = __half2float(gates[((size_t)b * Sn + t) * 2048 + (size_t)dir * 1024 + g]);
#pragma unroll 8
        for (int k = 0; k < Hn; k++)
            acc = fmaf(U[(size_t)k * Gn + g], hsh[k], acc);
        gsh[tid] = acc;
        __syncthreads();
        float* hw = (step & 1) ? hb1 : hb0;
        if (tid < 64) {
            float fi = sigf(gsh[tid]), ff = sigf(gsh[64 + tid]);
            float fg = tanhf(gsh[128 + tid]), fo = sigf(gsh[192 + tid]);
            c = ff * c + fi * fg;
            float h = fo * tanhf(c);
            hw[u0 + tid] = h;
            float o = (!mask || t < dl) ? h : 0.f;
            out[((size_t)b * Sn + t) * 512 + (size_t)dir * 256 + u0 + tid] = o;
        }
        __syncthreads();
        if (tid == 0) {
            __threadfence();
            atomicAdd(&mycnt[step], 1);
            while (atomicAdd(&mycnt[step], 0) < 4) { }
            __threadfence();
        }
        __syncthreads();
        hsh[tid] = hw[tid];
        __syncthreads();
    }
}

// ---------------- block reduction helper ----------------
__device__ __forceinline__ float blockReduce256(float v, volatile float* red)
{
#pragma unroll
    for (int o = 16; o > 0; o >>= 1) v += __shfl_down_sync(0xffffffffu, v, o);
    if ((threadIdx.x & 31) == 0) red[threadIdx.x >> 5] = v;
    __syncthreads();
    float r = red[0] + red[1] + red[2] + red[3] + red[4] + red[5] + red[6] + red[7];
    __syncthreads();
    return r;
}

// ---------------- restricted window attention ----------------
__global__ void __launch_bounds__(256) attn_kernel(const float* __restrict__ hs,
                                                   const float* __restrict__ attn_w,
                                                   const float* __restrict__ attn_b,
                                                   const int* __restrict__ dlen,
                                                   float* __restrict__ hr)
{
    __shared__ float red[8];
    __shared__ float sc[7];
    __shared__ float awt[7];
    int bs = blockIdx.x;
    int b = bs / Sn, s = bs % Sn;
    int tid = threadIdx.x;
    int dl = dlen[b];
    const float* X = hs + (size_t)bs * 512;

    float pxx = 0.f, pxw = 0.f;
    for (int d = tid; d < 512; d += 256) {
        float v = X[d];
        pxx += v * v;
        pxw += v * attn_w[512 + d];
    }
    float nx2 = blockReduce256(pxx, red);
    float xw2 = blockReduce256(pxw, red);
    float nxc = fmaxf(sqrtf(nx2), 1e-12f);

    for (int k = 0; k < 7; k++) {
        int idx = s - 3 + k;
        int idc = min(max(idx, 0), Sn - 1);
        const float* Xw = hs + ((size_t)b * Sn + idc) * 512;
        float pa = 0.f, pb = 0.f, pc = 0.f;
        for (int d = tid; d < 512; d += 256) {
            float w = Xw[d];
            pa += w * X[d];
            pb += w * w;
            pc += w * attn_w[d];
        }
        float dwx = blockReduce256(pa, red);
        float nw2 = blockReduce256(pb, red);
        float dw0 = blockReduce256(pc, red);
        if (tid == 0) {
            float sim = sigf(dwx / (fmaxf(sqrtf(nw2), 1e-12f) * nxc));
            float sco = dw0 + xw2 + sim * attn_w[1024] + attn_b[0];
            bool valid = (idx >= 0) && (idx < dl) && (s < dl);
            sc[k] = valid ? sco : -1e30f;
        }
    }
    __syncthreads();
    if (tid == 0) {
        float m = sc[0];
#pragma unroll
        for (int k = 1; k < 7; k++) m = fmaxf(m, sc[k]);
        float sum = 0.f;
#pragma unroll
        for (int k = 0; k < 7; k++) { float e = expf(sc[k] - m); awt[k] = e; sum += e; }
        float inv = 1.f / sum;
#pragma unroll
        for (int k = 0; k < 7; k++) awt[k] *= inv;
    }
    __syncthreads();
    for (int d = tid; d < 512; d += 256) {
        float acc = 0.f;
#pragma unroll
        for (int k = 0; k < 7; k++) {
            int idc = min(max(s - 3 + k, 0), Sn - 1);
            acc += awt[k] * hs[((size_t)b * Sn + idc) * 512 + d];
        }
        hr[(size_t)bs * 1024 + d] = X[d];
        hr[(size_t)bs * 1024 + 512 + d] = (s < dl) ? acc : 0.f;
    }
}

// ---------------- classifier + softmax(2) ----------------
__global__ void __launch_bounds__(128) cls_kernel(const float* __restrict__ h2,
                                                  const float* __restrict__ clsW,
                                                  const float* __restrict__ clsb,
                                                  float* __restrict__ out)
{
    __shared__ float r0s[4], r1s[4];
    int bs = blockIdx.x;
    int tid = threadIdx.x;
    const float* h = h2 + (size_t)bs * 512;
    float p0 = 0.f, p1 = 0.f;
    for (int d = tid; d < 512; d += 128) {
        float v = h[d];
        p0 += v * clsW[d];
        p1 += v * clsW[512 + d];
    }
#pragma unroll
    for (int o = 16; o > 0; o >>= 1) {
        p0 += __shfl_down_sync(0xffffffffu, p0, o);
        p1 += __shfl_down_sync(0xffffffffu, p1, o);
    }
    if ((tid & 31) == 0) { r0s[tid >> 5] = p0; r1s[tid >> 5] = p1; }
    __syncthreads();
    if (tid == 0) {
        float l0 = r0s[0] + r0s[1] + r0s[2] + r0s[3] + clsb[0];
        float l1 = r1s[0] + r1s[1] + r1s[2] + r1s[3] + clsb[1];
        float m = fmaxf(l0, l1);
        float e0 = expf(l0 - m), e1 = expf(l1 - m);
        float inv = 1.f / (e0 + e1);
        out[(size_t)bs * 2 + 0] = e0 * inv;
        out[(size_t)bs * 2 + 1] = e1 * inv;
    }
}

// ---------------- launch ----------------
extern "C" void kernel_launch(void* const* d_in, const int* in_sizes, int n_in,
                              void* d_out, int out_size)
{
    const float* x     = (const float*)d_in[0];
    const int*   slen  = (const int*)d_in[1];
    const int*   dlen  = (const int*)d_in[2];
    const float* wl_Wf = (const float*)d_in[3];
    const float* wl_Uf = (const float*)d_in[4];
    const float* wl_bf = (const float*)d_in[5];
    const float* wl_Wb = (const float*)d_in[6];
    const float* wl_Ub = (const float*)d_in[7];
    const float* wl_bb = (const float*)d_in[8];
    const float* sl_Wf = (const float*)d_in[9];
    const float* sl_Uf = (const float*)d_in[10];
    const float* sl_bf = (const float*)d_in[11];
    const float* sl_Wb = (const float*)d_in[12];
    const float* sl_Ub = (const float*)d_in[13];
    const float* sl_bb = (const float*)d_in[14];
    const float* attn_w = (const float*)d_in[15];
    const float* attn_b = (const float*)d_in[16];
    const float* m2_Wf = (const float*)d_in[17];
    const float* m2_Uf = (const float*)d_in[18];
    const float* m2_bf = (const float*)d_in[19];
    const float* m2_Wb = (const float*)d_in[20];
    const float* m2_Ub = (const float*)d_in[21];
    const float* m2_bb = (const float*)d_in[22];
    const float* cls_W = (const float*)d_in[23];
    const float* cls_b = (const float*)d_in[24];
    float* out = (float*)d_out;

    float *ut, *pl, *hs, *hr, *h2, *hbuf, *hwb;
    int *cnt0, *cnt1, *cnt2;
    __half *wg, *sg, *mg, *ah, *bh, *ubq;
    cudaGetSymbolAddress((void**)&wg, g_wgates);
    cudaGetSymbolAddress((void**)&ut, g_Ut);
    cudaGetSymbolAddress((void**)&pl, g_pooled);
    cudaGetSymbolAddress((void**)&sg, g_sgates);
    cudaGetSymbolAddress((void**)&hs, g_hs);
    cudaGetSymbolAddress((void**)&hr, g_hr);
    cudaGetSymbolAddress((void**)&mg, g_mgates);
    cudaGetSymbolAddress((void**)&h2, g_h2);
    cudaGetSymbolAddress((void**)&hbuf, g_hbuf);
    cudaGetSymbolAddress((void**)&hwb, g_hwb);
    cudaGetSymbolAddress((void**)&cnt0, g_cnt0);
    cudaGetSymbolAddress((void**)&cnt1, g_cnt1);
    cudaGetSymbolAddress((void**)&cnt2, g_cnt2);
    cudaGetSymbolAddress((void**)&ah, g_ah);
    cudaGetSymbolAddress((void**)&bh, g_bh);
    cudaGetSymbolAddress((void**)&ubq, g_ubq);

    cudaFuncSetAttribute(gemm_mma, cudaFuncAttributeMaxDynamicSharedMemorySize, 2 * STAGE_B);
    cudaFuncSetAttribute(lstm_word_p, cudaFuncAttributeMaxDynamicSharedMemorySize, LWP_SMEM);

    // barrier counters
    cudaMemsetAsync(cnt0, 0, 2 * 16 * 144 * sizeof(int));
    cudaMemsetAsync(cnt1, 0, 2 * 16 * 96 * sizeof(int));
    cudaMemsetAsync(cnt2, 0, 2 * 16 * 96 * sizeof(int));

    // --- kernels: [1] conv_all [2] conv_uq [3] gemm(word) [4] lstm_word_p (profiled) ---
    {
        size_t total = (size_t)NW * KPW + 2 * (size_t)1024 * KPW;
        conv_all<<<(int)((total + 255) / 256), 256>>>(x, wl_Wf, wl_Wb, ah, bh);
    }
    conv_uq<<<(2 * 4 * 256 * 256 + 255) / 256, 256>>>(wl_Uf, wl_Ub, ubq);
    gemm_mma<<<dim3(16, NW / 128), 256, 2 * STAGE_B>>>(ah, bh, wl_bf, wl_bb, wg, KPW);
    lstm_word_p<<<dim3(4, 16, 2), 512, LWP_SMEM>>>(wg, ubq, slen, dlen, pl, cnt0, hwb);

    // prep for sequence-level LSTMs
    transpose_u<<<dim3(32, 8, 4), dim3(32, 8)>>>(sl_Uf, sl_Ub, m2_Uf, m2_Ub, ut);

    // sentence-level: convert + GEMM + recurrence
    conv_w<<<(NSq * 512 + 255) / 256, 256>>>(pl, ah, NSq, 512, 512);
    conv_w<<<(1024 * 512 + 255) / 256, 256>>>(sl_Wf, bh, 1024, 512, 512);
    conv_w<<<(1024 * 512 + 255) / 256, 256>>>(sl_Wb, bh + 1024 * 512, 1024, 512, 512);
    gemm_mma<<<dim3(16, NSq / 128), 256, 2 * STAGE_B>>>(ah, bh, sl_bf, sl_bb, sg, 512);
    lstm_seq4<<<dim3(4, Bn, 2), 256>>>(sg, ut, 0, dlen, hs, 1, cnt1, hbuf);

    // restricted attention
    attn_kernel<<<NSq, 256>>>(hs, attn_w, attn_b, dlen, hr);

    // m2 level: convert + GEMM + recurrence
    conv_w<<<(NSq * 1024 + 255) / 256, 256>>>(hr, ah, NSq, 1024, 1024);
    conv_w<<<(1024 * 1024 + 255) / 256, 256>>>(m2_Wf, bh, 1024, 1024, 1024);
    conv_w<<<(1024 * 1024 + 255) / 256, 256>>>(m2_Wb, bh + 1024 * 1024, 1024, 1024, 1024);
    gemm_mma<<<dim3(16, NSq / 128), 256, 2 * STAGE_B>>>(ah, bh, m2_bf, m2_bb, mg, 1024);
    lstm_seq4<<<dim3(4, Bn, 2), 256>>>(mg, ut, 2, dlen, h2, 0, cnt2, hbuf);

    // classifier + softmax
    cls_kernel<<<NSq, 128>>>(h2, cls_W, cls_b, out);
}

// round 16
// speedup vs baseline: 1.0772x; 1.0084x over previous
#include <cuda_runtime.h>
#include <cuda_fp16.h>
#include <math.h>
#include <stdint.h>

// Problem dims
#define Bn 16
#define Sn 96
#define Wn 48
#define En 300
#define Hn 256
#define Gn 1024
#define NSq (Bn*Sn)      // 1536
#define NW  (NSq*Wn)     // 73728
#define KPW 320          // padded K for word-level GEMM

// ---------------- static device scratch ----------------
__device__ __align__(16) __half g_wgates[(size_t)NW * 2048];   // fp16 gates (word)
__device__ float g_Ut[4 * Hn * Gn];                  // sl/m2 recurrent weights, k-major fp32
__device__ float g_pooled[(size_t)NSq * 2 * Hn];
__device__ __align__(16) __half g_sgates[(size_t)NSq * 2048];
__device__ float g_hs[(size_t)NSq * 2 * Hn];
__device__ float g_hr[(size_t)NSq * 4 * Hn];
__device__ __align__(16) __half g_mgates[(size_t)NSq * 2048];
__device__ float g_h2[(size_t)NSq * 2 * Hn];
__device__ int   g_cnt0[2 * 16 * 144];
__device__ int   g_cnt1[2 * 16 * 96];
__device__ int   g_cnt2[2 * 16 * 96];
__device__ float g_hbuf[2 * 2 * 16 * 256];
__device__ __align__(4) __half g_hwb[2 * 16 * 2 * 32 * 256];  // word-level h exchange, fp16
__device__ __align__(16) __half g_ah[(size_t)NW * KPW];
__device__ __align__(16) __half g_bh[2048 * 1024];
__device__ __align__(16) __half g_ubq[2 * 4 * 256 * 256];  // word U [dir][quarter][localcol][k] fp16

__device__ __forceinline__ float sigf(float x) { return 1.0f / (1.0f + expf(-x)); }

__device__ __forceinline__ uint32_t smem_u32(const void* p) {
    uint32_t a;
    asm("{ .reg .u64 t; cvta.to.shared.u64 t, %1; cvt.u32.u64 %0, t; }" : "=r"(a) : "l"(p));
    return a;
}
__device__ __forceinline__ void cpasync16(uint32_t dst, const void* src) {
    asm volatile("cp.async.cg.shared.global [%0], [%1], 16;" :: "r"(dst), "l"(src));
}
__device__ __forceinline__ void ldsm4(uint32_t* r, uint32_t addr) {
    asm volatile("ldmatrix.sync.aligned.m8n8.x4.shared.b16 {%0,%1,%2,%3}, [%4];"
                 : "=r"(r[0]), "=r"(r[1]), "=r"(r[2]), "=r"(r[3]) : "r"(addr));
}
__device__ __forceinline__ void mma_f16(float* c, const uint32_t* a, const uint32_t* b) {
    asm volatile("mma.sync.aligned.m16n8k16.row.col.f32.f16.f16.f32 "
                 "{%0,%1,%2,%3}, {%4,%5,%6,%7}, {%8,%9}, {%0,%1,%2,%3};"
                 : "+f"(c[0]), "+f"(c[1]), "+f"(c[2]), "+f"(c[3])
                 : "r"(a[0]), "r"(a[1]), "r"(a[2]), "r"(a[3]), "r"(b[0]), "r"(b[1]));
}
__device__ __forceinline__ float ex2a(float x) { float y; asm("ex2.approx.f32 %0, %1;" : "=f"(y) : "f"(x)); return y; }
__device__ __forceinline__ float rcpa(float x) { float y; asm("rcp.approx.f32 %0, %1;" : "=f"(y) : "f"(x)); return y; }
__device__ __forceinline__ float fsig(float x) { return rcpa(1.0f + ex2a(-1.4426950408889634f * x)); }
__device__ __forceinline__ float ftanh(float x) { return 1.0f - 2.0f * rcpa(ex2a(2.8853900817779268f * x) + 1.0f); }

// spin barrier among `need` arrivals; poll with plain volatile loads (no atomic round-trips)
__device__ __forceinline__ void spin_barrier(int* slot, int need) {
    __threadfence();
    atomicAdd(slot, 1);
    volatile int* p = slot;
    while (*p < need) { }
    __threadfence();
}

// ---------------- fused word-level conversions: x -> ah, Wf|Wb -> bh ----------------
__global__ void conv_all(const float* __restrict__ x,
                         const float* __restrict__ wf, const float* __restrict__ wb,
                         __half* __restrict__ ah, __half* __restrict__ bh)
{
    size_t idx = (size_t)blockIdx.x * 256 + threadIdx.x;
    const size_t nA = (size_t)NW * KPW;
    const size_t nW = (size_t)1024 * KPW;
    if (idx < nA) {
        size_t m = idx / KPW;
        int k = (int)(idx - m * KPW);
        ah[idx] = __float2half((k < En) ? x[m * En + k] : 0.f);
    } else if (idx < nA + nW) {
        size_t i = idx - nA;
        size_t m = i / KPW;
        int k = (int)(i - m * KPW);
        bh[i] = __float2half((k < En) ? wf[m * En + k] : 0.f);
    } else if (idx < nA + 2 * nW) {
        size_t i = idx - nA - nW;
        size_t m = i / KPW;
        int k = (int)(i - m * KPW);
        bh[nW + i] = __float2half((k < En) ? wb[m * En + k] : 0.f);
    }
}

// ---------------- fp32 -> fp16 single with K padding ----------------
__global__ void conv_w(const float* __restrict__ src, __half* __restrict__ dst,
                       int M, int K, int Kp)
{
    size_t idx = (size_t)blockIdx.x * 256 + threadIdx.x;
    if (idx >= (size_t)M * Kp) return;
    size_t m = idx / Kp;
    int k = (int)(idx - m * Kp);
    float v = (k < K) ? src[m * K + k] : 0.f;
    dst[idx] = __float2half(v);
}

// word-level recurrent U -> per-quarter layout [dir][q][localcol(gate*64+ul)][k]
__global__ void conv_uq(const float* __restrict__ uf, const float* __restrict__ ub,
                        __half* __restrict__ dst)
{
    int idx = blockIdx.x * 256 + threadIdx.x;
    if (idx >= 2 * 4 * 256 * 256) return;
    int dir = idx >> 18;
    int rem = idx & 262143;
    int q = rem >> 16;
    int rem2 = rem & 65535;
    int lc = rem2 >> 8;
    int k  = rem2 & 255;
    int gate = lc >> 6, ul = lc & 63;
    int gcol = gate * 256 + q * 64 + ul;
    const float* U = dir ? ub : uf;
    dst[idx] = __float2half(U[gcol * 256 + k]);
}

// ---------------- transpose U (1024x256 -> 256x1024), 4 matrices (sl/m2, fp32) ----------------
__global__ void transpose_u(const float* __restrict__ u0, const float* __restrict__ u1,
                            const float* __restrict__ u2, const float* __restrict__ u3,
                            float* __restrict__ ut)
{
    __shared__ float tile[32][33];
    int m = blockIdx.z;
    const float* U = (m == 0) ? u0 : (m == 1) ? u1 : (m == 2) ? u2 : u3;
    int g0 = blockIdx.x * 32;
    int k0 = blockIdx.y * 32;
    int tx = threadIdx.x, ty = threadIdx.y;
#pragma unroll
    for (int i = 0; i < 4; i++)
        tile[ty + 8 * i][tx] = U[(size_t)(g0 + ty + 8 * i) * Hn + k0 + tx];
    __syncthreads();
    float* Ut = ut + (size_t)m * Hn * Gn;
#pragma unroll
    for (int i = 0; i < 4; i++)
        Ut[(size_t)(k0 + ty + 8 * i) * Gn + g0 + tx] = tile[tx][ty + 8 * i];
}

// ---------------- fp16 GEMM via mma.sync: C(half) = A @ B^T + bias ----------------
#define STAGE_B   20480
#define OFF_BH    10240

__global__ void __launch_bounds__(256, 2) gemm_mma(
    const __half* __restrict__ Ah, const __half* __restrict__ Bh,
    const float* __restrict__ biasF, const float* __restrict__ biasB,
    __half* __restrict__ C, int Kp)
{
    extern __shared__ char smem[];
    uint32_t sb = smem_u32(smem);
    int tid = threadIdx.x;
    int lane = tid & 31, wid = tid >> 5;
    int m0 = blockIdx.y * 128;
    int n0 = blockIdx.x * 128;
    int wm = (wid & 1) * 64;
    int wn = (wid >> 1) * 32;
    int nk = Kp / 32;

    float acc[4][4][4];
#pragma unroll
    for (int i = 0; i < 4; i++)
#pragma unroll
        for (int j = 0; j < 4; j++)
#pragma unroll
            for (int k = 0; k < 4; k++) acc[i][j][k] = 0.f;

    int ur = tid >> 2;
    int uc = tid & 3;

    auto load_stage = [&](int kc, int buf) {
        uint32_t dbase = sb + buf * STAGE_B;
#pragma unroll
        for (int rep = 0; rep < 2; rep++) {
            int r = ur + rep * 64;
            uint32_t doff = (uint32_t)r * 80 + uc * 16;
            size_t srcA = (size_t)(m0 + r) * Kp + kc * 32 + uc * 8;
            size_t srcB = (size_t)(n0 + r) * Kp + kc * 32 + uc * 8;
            cpasync16(dbase + doff,          Ah + srcA);
            cpasync16(dbase + OFF_BH + doff, Bh + srcB);
        }
    };

    load_stage(0, 0);
    asm volatile("cp.async.commit_group;" ::: "memory");

#pragma unroll 1
    for (int kc = 0; kc < nk; kc++) {
        if (kc + 1 < nk) load_stage(kc + 1, (kc + 1) & 1);
        asm volatile("cp.async.commit_group;" ::: "memory");
        asm volatile("cp.async.wait_group 1;" ::: "memory");
        __syncthreads();

        uint32_t base = sb + (kc & 1) * STAGE_B;
#pragma unroll
        for (int kk = 0; kk < 32; kk += 16) {
            uint32_t ah[4][4];
#pragma unroll
            for (int mt = 0; mt < 4; mt++) {
                int row = wm + mt * 16 + (lane & 15);
                int col = kk + ((lane >> 4) << 3);
                ldsm4(ah[mt], base + (uint32_t)row * 80 + col * 2);
            }
            uint32_t bh[2][4];
#pragma unroll
            for (int bt = 0; bt < 2; bt++) {
                int row = wn + bt * 16 + ((lane >> 4) << 3) + (lane & 7);
                int col = kk + (((lane >> 3) & 1) << 3);
                ldsm4(bh[bt], base + OFF_BH + (uint32_t)row * 80 + col * 2);
            }
#pragma unroll
            for (int mt = 0; mt < 4; mt++) {
#pragma unroll
                for (int nt = 0; nt < 4; nt++) {
                    const uint32_t* fh = &bh[nt >> 1][(nt & 1) * 2];
                    mma_f16(acc[mt][nt], ah[mt], fh);
                }
            }
        }
        __syncthreads();
    }

    const float* bp = (n0 < 1024) ? (biasF + n0) : (biasB + (n0 - 1024));
#pragma unroll
    for (int mt = 0; mt < 4; mt++) {
        int r0 = m0 + wm + mt * 16 + (lane >> 2);
#pragma unroll
        for (int nt = 0; nt < 4; nt++) {
            int col = wn + nt * 8 + 2 * (lane & 3);
            float2 bv = *(const float2*)(bp + col);
            __half2 v0 = __floats2half2_rn(acc[mt][nt][0] + bv.x, acc[mt][nt][1] + bv.y);
            __half2 v1 = __floats2half2_rn(acc[mt][nt][2] + bv.x, acc[mt][nt][3] + bv.y);
            *(__half2*)&C[(size_t)r0 * 2048 + n0 + col] = v0;
            *(__half2*)&C[(size_t)(r0 + 8) * 2048 + n0 + col] = v1;
        }
    }
}

// ---------------- word-level LSTM, persistent-U: 128 blocks (4 quarters x 16 slots x 2 dirs) ----------------
// SMEM: US 256x528 @0 (persistent U slice); HA 32x528 @135168; G 32x264 fp32 @152064; lens @185856.
#define LWP_HA    135168
#define LWP_G     152064
#define LWP_LEN   185856
#define LWP_SMEM  185984

__global__ void __launch_bounds__(512, 1) lstm_word_p(
    const __half* __restrict__ gates, const __half* __restrict__ ubq,
    const int* __restrict__ slen, const int* __restrict__ dlen,
    float* __restrict__ pooled, int* __restrict__ cnt, __half* __restrict__ hwb)
{
    extern __shared__ char sm[];
    uint32_t sb = smem_u32(sm);
    int tid = threadIdx.x;
    int lane = tid & 31, wid = tid >> 5;   // 16 warps
    int q = blockIdx.x;       // unit quarter 0..3
    int slot = blockIdx.y;    // 0..15
    int dir = blockIdx.z;

    // one-time load of this block's U slice (256 rows x 512B) into padded smem
    {
        const __half* src = ubq + ((size_t)(dir * 4 + q) * 256) * 256;
#pragma unroll
        for (int i = 0; i < 16; i++) {
            int idx = i * 512 + tid;          // 0..8191
            int row = idx >> 5, seg = idx & 31;
            cpasync16(sb + (uint32_t)row * 528 + seg * 16, src + (size_t)row * 256 + seg * 8);
        }
        asm volatile("cp.async.commit_group;" ::: "memory");
        asm volatile("cp.async.wait_group 0;" ::: "memory");
    }
    __syncthreads();

    float* Gs = (float*)(sm + LWP_G);
    int* lensh = (int*)(sm + LWP_LEN);
    int* mycnt = cnt + (dir * 16 + slot) * 144;
    __half* hb0 = hwb + ((size_t)(dir * 16 + slot) * 2 + 0) * 8192;
    __half* hb1 = hwb + ((size_t)(dir * 16 + slot) * 2 + 1) * 8192;

    int u = tid & 63, sgrp = tid >> 6;   // thread owns unit u for seqs sgrp*4..sgrp*4+3
    int wn = wid * 16;                   // warp's 16 local gate-cols

#pragma unroll 1
    for (int g = 0; g < 3; g++) {
        int ng = g * 16 + slot;
        int n0 = ng * 32;

        for (int i = tid; i < 16896 / 4; i += 512) ((float*)(sm + LWP_HA))[i] = 0.f;
        if (tid < 32) lensh[tid] = slen[n0 + tid];
        float c[4], hm[4];
#pragma unroll
        for (int i = 0; i < 4; i++) { c[i] = 0.f; hm[i] = -INFINITY; }
        __syncthreads();

#pragma unroll 1
        for (int step = 0; step < Wn; ++step) {
            int t = dir ? (Wn - 1 - step) : step;

            // recurrent mma: G[32 x 256cols] = HA(h prev, fp16) @ US^T
            float acc[2][2][4];
#pragma unroll
            for (int mt = 0; mt < 2; mt++)
#pragma unroll
                for (int nt = 0; nt < 2; nt++)
#pragma unroll
                    for (int k = 0; k < 4; k++) acc[mt][nt][k] = 0.f;

#pragma unroll
            for (int kc = 0; kc < 16; kc++) {
                uint32_t ah[2][4];
#pragma unroll
                for (int mt = 0; mt < 2; mt++) {
                    int row = mt * 16 + (lane & 15);
                    int col = kc * 16 + ((lane >> 4) << 3);
                    ldsm4(ah[mt], sb + LWP_HA + (uint32_t)row * 528 + col * 2);
                }
                uint32_t bf[4];
                {
                    int row = wn + ((lane >> 4) << 3) + (lane & 7);
                    int col = kc * 16 + (((lane >> 3) & 1) << 3);
                    ldsm4(bf, sb + (uint32_t)row * 528 + col * 2);
                }
#pragma unroll
                for (int mt = 0; mt < 2; mt++)
#pragma unroll
                    for (int nt = 0; nt < 2; nt++)
                        mma_f16(acc[mt][nt], ah[mt], &bf[nt * 2]);
            }

            // stage G
#pragma unroll
            for (int mt = 0; mt < 2; mt++) {
                int row0 = mt * 16 + (lane >> 2);
#pragma unroll
                for (int nt = 0; nt < 2; nt++) {
                    int colb = wn + nt * 8 + (lane & 3) * 2;
                    Gs[row0 * 264 + colb]     = acc[mt][nt][0];
                    Gs[row0 * 264 + colb + 1] = acc[mt][nt][1];
                    Gs[(row0 + 8) * 264 + colb]     = acc[mt][nt][2];
                    Gs[(row0 + 8) * 264 + colb + 1] = acc[mt][nt][3];
                }
            }
            __syncthreads();

            // activations: thread (u, sgrp) handles 4 seqs, h written fp16 directly
            __half* hw = (step & 1) ? hb1 : hb0;
#pragma unroll
            for (int i = 0; i < 4; i++) {
                int s = sgrp * 4 + i;
                const __half* gp = gates + (((size_t)(n0 + s)) * Wn + t) * 2048 + (size_t)dir * 1024;
                float ai = __half2float(gp[0 * 256 + q * 64 + u]) + Gs[s * 264 + 0 * 64 + u];
                float af = __half2float(gp[1 * 256 + q * 64 + u]) + Gs[s * 264 + 1 * 64 + u];
                float ag = __half2float(gp[2 * 256 + q * 64 + u]) + Gs[s * 264 + 2 * 64 + u];
                float ao = __half2float(gp[3 * 256 + q * 64 + u]) + Gs[s * 264 + 3 * 64 + u];
                c[i] = fsig(af) * c[i] + fsig(ai) * ftanh(ag);
                float h = fsig(ao) * ftanh(c[i]);
                if (t < lensh[s]) hm[i] = fmaxf(hm[i], h);
                hw[s * 256 + q * 64 + u] = __float2half(h);
            }
            __syncthreads();

            // cross-block barrier among the 4 quarter blocks (volatile poll)
            if (tid == 0) spin_barrier(&mycnt[g * 48 + step], 4);
            __syncthreads();

            // gather full h into HA (fp16, 2 halves per iteration per thread)
            const uint32_t* hw32 = (const uint32_t*)hw;
#pragma unroll
            for (int i = 0; i < 8; i++) {
                int ii = i * 512 + tid;     // 0..4095
                int s = ii >> 7, p = ii & 127;
                *(uint32_t*)(sm + LWP_HA + (size_t)s * 528 + p * 4) = hw32[s * 128 + p];
            }
            __syncthreads();
        }

        // pooled max for this block's units
#pragma unroll
        for (int i = 0; i < 4; i++) {
            int s = sgrp * 4 + i;
            int n = n0 + s;
            int bb = n / Sn, sr = n % Sn;
            float v = (sr < dlen[bb]) ? hm[i] : 0.f;
            pooled[(size_t)n * 512 + (size_t)dir * 256 + q * 64 + u] = v;
        }
        __syncthreads();
    }
}

// ---------------- sequence-level LSTM: 4-way N-split, global spin barrier per step ----------------
__global__ void __launch_bounds__(256) lstm_seq4(const __half* __restrict__ gates,
                                                 const float* __restrict__ ut, int ubase,
                                                 const int* __restrict__ dlen,
                                                 float* __restrict__ out, int mask,
                                                 int* __restrict__ cnt, float* __restrict__ hbuf)
{
    int ns = blockIdx.x;     // 0..3
    int b = blockIdx.y;
    int dir = blockIdx.z;
    int tid = threadIdx.x;
    int u0 = ns * 64;
    int gate = tid >> 6, ul = tid & 63;
    int g = gate * 256 + u0 + ul;
    const float* U = ut + (size_t)(ubase + dir) * Hn * Gn;
    __shared__ float hsh[256];
    __shared__ float gsh[256];
    float c = 0.f;
    int dl = dlen[b];
    float* hb0 = hbuf + ((size_t)(0 * 2 + dir) * 16 + b) * 256;
    float* hb1 = hbuf + ((size_t)(1 * 2 + dir) * 16 + b) * 256;
    int* mycnt = cnt + (dir * 16 + b) * 96;
    hsh[tid] = 0.f;
    __syncthreads();

#pragma unroll 1
    for (int step = 0; step < Sn; ++step) {
        int t = dir ? (Sn - 1 - step) : step;
        float acc = __half2float(gates[((size_t)b * Sn + t) * 2048 + (size_t)dir * 1024 + g]);
#pragma unroll 8
        for (int k = 0; k < Hn; k++)
            acc = fmaf(U[(size_t)k * Gn + g], hsh[k], acc);
        gsh[tid] = acc;
        __syncthreads();
        float* hw = (step & 1) ? hb1 : hb0;
        if (tid < 64) {
            float fi = sigf(gsh[tid]), ff = sigf(gsh[64 + tid]);
            float fg = tanhf(gsh[128 + tid]), fo = sigf(gsh[192 + tid]);
            c = ff * c + fi * fg;
            float h = fo * tanhf(c);
            hw[u0 + tid] = h;
            float o = (!mask || t < dl) ? h : 0.f;
            out[((size_t)b * Sn + t) * 512 + (size_t)dir * 256 + u0 + tid] = o;
        }
        __syncthreads();
        if (tid == 0) spin_barrier(&mycnt[step], 4);
        __syncthreads();
        hsh[tid] = hw[tid];
        __syncthreads();
    }
}

// ---------------- block reduction helper ----------------
__device__ __forceinline__ float blockReduce256(float v, volatile float* red)
{
#pragma unroll
    for (int o = 16; o > 0; o >>= 1) v += __shfl_down_sync(0xffffffffu, v, o);
    if ((threadIdx.x & 31) == 0) red[threadIdx.x >> 5] = v;
    __syncthreads();
    float r = red[0] + red[1] + red[2] + red[3] + red[4] + red[5] + red[6] + red[7];
    __syncthreads();
    return r;
}

// ---------------- restricted window attention ----------------
__global__ void __launch_bounds__(256) attn_kernel(const float* __restrict__ hs,
                                                   const float* __restrict__ attn_w,
                                                   const float* __restrict__ attn_b,
                                                   const int* __restrict__ dlen,
                                                   float* __restrict__ hr)
{
    __shared__ float red[8];
    __shared__ float sc[7];
    __shared__ float awt[7];
    int bs = blockIdx.x;
    int b = bs / Sn, s = bs % Sn;
    int tid = threadIdx.x;
    int dl = dlen[b];
    const float* X = hs + (size_t)bs * 512;

    float pxx = 0.f, pxw = 0.f;
    for (int d = tid; d < 512; d += 256) {
        float v = X[d];
        pxx += v * v;
        pxw += v * attn_w[512 + d];
    }
    float nx2 = blockReduce256(pxx, red);
    float xw2 = blockReduce256(pxw, red);
    float nxc = fmaxf(sqrtf(nx2), 1e-12f);

    for (int k = 0; k < 7; k++) {
        int idx = s - 3 + k;
        int idc = min(max(idx, 0), Sn - 1);
        const float* Xw = hs + ((size_t)b * Sn + idc) * 512;
        float pa = 0.f, pb = 0.f, pc = 0.f;
        for (int d = tid; d < 512; d += 256) {
            float w = Xw[d];
            pa += w * X[d];
            pb += w * w;
            pc += w * attn_w[d];
        }
        float dwx = blockReduce256(pa, red);
        float nw2 = blockReduce256(pb, red);
        float dw0 = blockReduce256(pc, red);
        if (tid == 0) {
            float sim = sigf(dwx / (fmaxf(sqrtf(nw2), 1e-12f) * nxc));
            float sco = dw0 + xw2 + sim * attn_w[1024] + attn_b[0];
            bool valid = (idx >= 0) && (idx < dl) && (s < dl);
            sc[k] = valid ? sco : -1e30f;
        }
    }
    __syncthreads();
    if (tid == 0) {
        float m = sc[0];
#pragma unroll
        for (int k = 1; k < 7; k++) m = fmaxf(m, sc[k]);
        float sum = 0.f;
#pragma unroll
        for (int k = 0; k < 7; k++) { float e = expf(sc[k] - m); awt[k] = e; sum += e; }
        float inv = 1.f / sum;
#pragma unroll
        for (int k = 0; k < 7; k++) awt[k] *= inv;
    }
    __syncthreads();
    for (int d = tid; d < 512; d += 256) {
        float acc = 0.f;
#pragma unroll
        for (int k = 0; k < 7; k++) {
            int idc = min(max(s - 3 + k, 0), Sn - 1);
            acc += awt[k] * hs[((size_t)b * Sn + idc) * 512 + d];
        }
        hr[(size_t)bs * 1024 + d] = X[d];
        hr[(size_t)bs * 1024 + 512 + d] = (s < dl) ? acc : 0.f;
    }
}

// ---------------- classifier + softmax(2) ----------------
__global__ void __launch_bounds__(128) cls_kernel(const float* __restrict__ h2,
                                                  const float* __restrict__ clsW,
                                                  const float* __restrict__ clsb,
                                                  float* __restrict__ out)
{
    __shared__ float r0s[4], r1s[4];
    int bs = blockIdx.x;
    int tid = threadIdx.x;
    const float* h = h2 + (size_t)bs * 512;
    float p0 = 0.f, p1 = 0.f;
    for (int d = tid; d < 512; d += 128) {
        float v = h[d];
        p0 += v * clsW[d];
        p1 += v * clsW[512 + d];
    }
#pragma unroll
    for (int o = 16; o > 0; o >>= 1) {
        p0 += __shfl_down_sync(0xffffffffu, p0, o);
        p1 += __shfl_down_sync(0xffffffffu, p1, o);
    }
    if ((tid & 31) == 0) { r0s[tid >> 5] = p0; r1s[tid >> 5] = p1; }
    __syncthreads();
    if (tid == 0) {
        float l0 = r0s[0] + r0s[1] + r0s[2] + r0s[3] + clsb[0];
        float l1 = r1s[0] + r1s[1] + r1s[2] + r1s[3] + clsb[1];
        float m = fmaxf(l0, l1);
        float e0 = expf(l0 - m), e1 = expf(l1 - m);
        float inv = 1.f / (e0 + e1);
        out[(size_t)bs * 2 + 0] = e0 * inv;
        out[(size_t)bs * 2 + 1] = e1 * inv;
    }
}

// ---------------- launch ----------------
extern "C" void kernel_launch(void* const* d_in, const int* in_sizes, int n_in,
                              void* d_out, int out_size)
{
    const float* x     = (const float*)d_in[0];
    const int*   slen  = (const int*)d_in[1];
    const int*   dlen  = (const int*)d_in[2];
    const float* wl_Wf = (const float*)d_in[3];
    const float* wl_Uf = (const float*)d_in[4];
    const float* wl_bf = (const float*)d_in[5];
    const float* wl_Wb = (const float*)d_in[6];
    const float* wl_Ub = (const float*)d_in[7];
    const float* wl_bb = (const float*)d_in[8];
    const float* sl_Wf = (const float*)d_in[9];
    const float* sl_Uf = (const float*)d_in[10];
    const float* sl_bf = (const float*)d_in[11];
    const float* sl_Wb = (const float*)d_in[12];
    const float* sl_Ub = (const float*)d_in[13];
    const float* sl_bb = (const float*)d_in[14];
    const float* attn_w = (const float*)d_in[15];
    const float* attn_b = (const float*)d_in[16];
    const float* m2_Wf = (const float*)d_in[17];
    const float* m2_Uf = (const float*)d_in[18];
    const float* m2_bf = (const float*)d_in[19];
    const float* m2_Wb = (const float*)d_in[20];
    const float* m2_Ub = (const float*)d_in[21];
    const float* m2_bb = (const float*)d_in[22];
    const float* cls_W = (const float*)d_in[23];
    const float* cls_b = (const float*)d_in[24];
    float* out = (float*)d_out;

    float *ut, *pl, *hs, *hr, *h2, *hbuf;
    int *cnt0, *cnt1, *cnt2;
    __half *wg, *sg, *mg, *ah, *bh, *ubq, *hwb;
    cudaGetSymbolAddress((void**)&wg, g_wgates);
    cudaGetSymbolAddress((void**)&ut, g_Ut);
    cudaGetSymbolAddress((void**)&pl, g_pooled);
    cudaGetSymbolAddress((void**)&sg, g_sgates);
    cudaGetSymbolAddress((void**)&hs, g_hs);
    cudaGetSymbolAddress((void**)&hr, g_hr);
    cudaGetSymbolAddress((void**)&mg, g_mgates);
    cudaGetSymbolAddress((void**)&h2, g_h2);
    cudaGetSymbolAddress((void**)&hbuf, g_hbuf);
    cudaGetSymbolAddress((void**)&hwb, g_hwb);
    cudaGetSymbolAddress((void**)&cnt0, g_cnt0);
    cudaGetSymbolAddress((void**)&cnt1, g_cnt1);
    cudaGetSymbolAddress((void**)&cnt2, g_cnt2);
    cudaGetSymbolAddress((void**)&ah, g_ah);
    cudaGetSymbolAddress((void**)&bh, g_bh);
    cudaGetSymbolAddress((void**)&ubq, g_ubq);

    cudaFuncSetAttribute(gemm_mma, cudaFuncAttributeMaxDynamicSharedMemorySize, 2 * STAGE_B);
    cudaFuncSetAttribute(lstm_word_p, cudaFuncAttributeMaxDynamicSharedMemorySize, LWP_SMEM);

    // barrier counters
    cudaMemsetAsync(cnt0, 0, 2 * 16 * 144 * sizeof(int));
    cudaMemsetAsync(cnt1, 0, 2 * 16 * 96 * sizeof(int));
    cudaMemsetAsync(cnt2, 0, 2 * 16 * 96 * sizeof(int));

    // --- kernels: [1] conv_all [2] conv_uq [3] gemm(word) [4] lstm_word_p (profiled) ---
    {
        size_t total = (size_t)NW * KPW + 2 * (size_t)1024 * KPW;
        conv_all<<<(int)((total + 255) / 256), 256>>>(x, wl_Wf, wl_Wb, ah, bh);
    }
    conv_uq<<<(2 * 4 * 256 * 256 + 255) / 256, 256>>>(wl_Uf, wl_Ub, ubq);
    gemm_mma<<<dim3(16, NW / 128), 256, 2 * STAGE_B>>>(ah, bh, wl_bf, wl_bb, wg, KPW);
    lstm_word_p<<<dim3(4, 16, 2), 512, LWP_SMEM>>>(wg, ubq, slen, dlen, pl, cnt0, hwb);

    // prep for sequence-level LSTMs
    transpose_u<<<dim3(32, 8, 4), dim3(32, 8)>>>(sl_Uf, sl_Ub, m2_Uf, m2_Ub, ut);

    // sentence-level: convert + GEMM + recurrence
    conv_w<<<(NSq * 512 + 255) / 256, 256>>>(pl, ah, NSq, 512, 512);
    conv_w<<<(1024 * 512 + 255) / 256, 256>>>(sl_Wf, bh, 1024, 512, 512);
    conv_w<<<(1024 * 512 + 255) / 256, 256>>>(sl_Wb, bh + 1024 * 512, 1024, 512, 512);
    gemm_mma<<<dim3(16, NSq / 128), 256, 2 * STAGE_B>>>(ah, bh, sl_bf, sl_bb, sg, 512);
    lstm_seq4<<<dim3(4, Bn, 2), 256>>>(sg, ut, 0, dlen, hs, 1, cnt1, hbuf);

    // restricted attention
    attn_kernel<<<NSq, 256>>>(hs, attn_w, attn_b, dlen, hr);

    // m2 level: convert + GEMM + recurrence
    conv_w<<<(NSq * 1024 + 255) / 256, 256>>>(hr, ah, NSq, 1024, 1024);
    conv_w<<<(1024 * 1024 + 255) / 256, 256>>>(m2_Wf, bh, 1024, 1024, 1024);
    conv_w<<<(1024 * 1024 + 255) / 256, 256>>>(m2_Wb, bh + 1024 * 1024, 1024, 1024, 1024);
    gemm_mma<<<dim3(16, NSq / 128), 256, 2 * STAGE_B>>>(ah, bh, m2_bf, m2_bb, mg, 1024);
    lstm_seq4<<<dim3(4, Bn, 2), 256>>>(mg, ut, 2, dlen, h2, 0, cnt2, hbuf);

    // classifier + softmax
    cls_kernel<<<NSq, 128>>>(h2, cls_W, cls_b, out);
}